// round 16
// baseline (speedup 1.0000x reference)
#include <cuda_runtime.h>

#define NEL 16777216   // B*C*D*H*W
typedef unsigned long long u64;

// Scratch: q/k/v in attention layout [b][s][head][d][e].
__device__ __align__(16) float g_q[NEL];
__device__ __align__(16) float g_k[NEL];
__device__ __align__(16) float g_v[NEL];

__device__ __forceinline__ u64 pk2(float lo, float hi) {
    u64 r; asm("mov.b64 %0, {%1,%2};" : "=l"(r) : "f"(lo), "f"(hi)); return r;
}
__device__ __forceinline__ float2 upk2(u64 v) {
    float2 r; asm("mov.b64 {%0,%1}, %2;" : "=f"(r.x), "=f"(r.y) : "l"(v)); return r;
}
#define FMA2(d, a, b) asm("fma.rn.f32x2 %0, %1, %2, %0;" : "+l"(d) : "l"(a), "l"(b))

// ---------------------------------------------------------------------------
// W[64][64] ([o][k]) -> two conflict-free planes, 16B stride over ot. (proven)
// ---------------------------------------------------------------------------
__device__ __forceinline__ void stage_W2(float* A, float* B,
                                         const float* __restrict__ Wsrc) {
    for (int idx = threadIdx.x; idx < 2048; idx += 256) {
        int k = idx >> 5, t = idx & 31;
        int ot = t >> 2, j = t & 3;
        A[idx] = Wsrc[(ot*8 + j)*64 + k];
        B[idx] = Wsrc[(ot*8 + 4 + j)*64 + k];
    }
}

__device__ __forceinline__ void stage_chunk(float* xs, const float* __restrict__ xsrc,
                                            int b, int n0, int kc) {
    const float4* xg = (const float4*)(xsrc + (u64)b*8388608 + n0);
    float4* xs4 = (float4*)xs;
    #pragma unroll
    for (int i = 0; i < 8; i++) {
        int idx = threadIdx.x + i*256;
        int c = idx >> 6, n4 = idx & 63;
        xs4[c*64 + n4] = xg[(u64)(kc*32 + c)*32768 + n4];
    }
}

// ---------------------------------------------------------------------------
// Q/K/V projection (proven structure; occupancy raised to 3 CTA/SM).
// ---------------------------------------------------------------------------
__global__ void __launch_bounds__(256, 3) k_proj(const float* __restrict__ x,
                                                 const float* __restrict__ W,
                                                 int which)
{
    __shared__ __align__(16) float xs[32*256];
    __shared__ __align__(16) float WA[2048];
    __shared__ __align__(16) float WB[2048];
    float* dst = (which == 0) ? g_q : (which == 1) ? g_k : g_v;
    int b = blockIdx.x >> 9;
    int n0 = (blockIdx.x & 511) << 8;
    stage_W2(WA, WB, W);

    int ot = threadIdx.x & 7, nt = threadIdx.x >> 3;
    u64 acc[8][4];
    #pragma unroll
    for (int o = 0; o < 8; o++)
        #pragma unroll
        for (int np = 0; np < 4; np++) acc[o][np] = 0ull;

    #pragma unroll 1
    for (int kc = 0; kc < 2; kc++) {
        __syncthreads();
        stage_chunk(xs, x, b, n0, kc);
        __syncthreads();
        #pragma unroll 4
        for (int k = 0; k < 32; k++) {
            int kg = kc*32 + k;
            float4 wa = *(const float4*)&WA[kg*32 + ot*4];
            float4 wb = *(const float4*)&WB[kg*32 + ot*4];
            u64 ws[8] = {pk2(wa.x,wa.x), pk2(wa.y,wa.y), pk2(wa.z,wa.z), pk2(wa.w,wa.w),
                         pk2(wb.x,wb.x), pk2(wb.y,wb.y), pk2(wb.z,wb.z), pk2(wb.w,wb.w)};
            const ulonglong2* xp = (const ulonglong2*)&xs[k*256 + nt*8];
            ulonglong2 x0 = xp[0], x1 = xp[1];
            u64 xv[4] = {x0.x, x0.y, x1.x, x1.y};
            #pragma unroll
            for (int o = 0; o < 8; o++)
                #pragma unroll
                for (int np = 0; np < 4; np++)
                    FMA2(acc[o][np], ws[o], xv[np]);
        }
    }

    int d = n0 >> 12;
    int sb = (n0 & 4095) + nt*8;
    float* gq = dst + (u64)b*8388608 + ot*256 + d*8;
    #pragma unroll
    for (int np = 0; np < 4; np++) {
        float2 f[8];
        #pragma unroll
        for (int o = 0; o < 8; o++) f[o] = upk2(acc[o][np]);
        float* p0 = gq + (u64)(sb + 2*np)*2048;
        ((float4*)p0)[0] = make_float4(f[0].x, f[1].x, f[2].x, f[3].x);
        ((float4*)p0)[1] = make_float4(f[4].x, f[5].x, f[6].x, f[7].x);
        float* p1 = gq + (u64)(sb + 2*np + 1)*2048;
        ((float4*)p1)[0] = make_float4(f[0].y, f[1].y, f[2].y, f[3].y);
        ((float4*)p1)[1] = make_float4(f[4].y, f[5].y, f[6].y, f[7].y);
    }
}

// ---------------------------------------------------------------------------
// Fused attention + O projection, occupancy-oriented shape.
// Block = (b, 4 consecutive s, all 8 heads), 256 threads = 8 warps.
// Warp w: sw = w&3, hh = w>>2; handles heads hh*4..hh*4+3 with the proven
// 1-D per-unit loop (R14). ctx -> sctx[c*132 + d*4 + sw]; epilogue GEMM
// [4o x 8loc] applies Wo -> out. smem = 66KB -> 3 CTA/SM (24 warps).
// ---------------------------------------------------------------------------
__global__ void __launch_bounds__(256) k_attn_o(const float* __restrict__ Wo,
                                                float* __restrict__ out)
{
    extern __shared__ __align__(16) float sm[];
    int tid = threadIdx.x;
    int warp = tid >> 5, lane = tid & 31;
    float* ksw  = sm + warp*256;           // per-warp K tile (8 warps x 256)
    float* vsw  = sm + 2048 + warp*256;    // per-warp V tile
    float* sctx = sm + 4096;               // [c][d*4 + sw], stride 132
    float* WT   = sm + 4096 + 8448;        // WT[k*64 + o]

    int sw = warp & 3, hh = warp >> 2;
    int blk = blockIdx.x;
    int s4 = blk & 1023, b = blk >> 10;
    int s = s4*4 + sw;

    for (int idx = tid; idx < 4096; idx += 256)
        WT[idx] = Wo[(idx & 63)*64 + (idx >> 6)];

    const float CEXP = 0.35355339059327373f * 1.4426950408889634f;

    #pragma unroll 1
    for (int hi = 0; hi < 4; hi++) {
        int head = hh*4 + hi;
        u64 u = (u64)(((b << 12) + s)*8 + head);

        __syncwarp();   // previous iteration's reads of ksw/vsw complete
        {
            const float4* kp = (const float4*)(g_k + u*256);
            const float4* vp = (const float4*)(g_v + u*256);
            ((float4*)ksw)[lane*2]     = kp[lane*2];
            ((float4*)ksw)[lane*2 + 1] = kp[lane*2 + 1];
            ((float4*)vsw)[lane*2]     = vp[lane*2];
            ((float4*)vsw)[lane*2 + 1] = vp[lane*2 + 1];
        }
        const float4* qp = (const float4*)(g_q + u*256 + lane*8);
        float4 q0 = qp[0], q1 = qp[1];
        u64 qv0 = pk2(q0.x, q0.y), qv1 = pk2(q0.z, q0.w);
        u64 qv2 = pk2(q1.x, q1.y), qv3 = pk2(q1.z, q1.w);
        __syncwarp();

        float ssA = 0.f, ssB = 0.f;
        u64 c0 = 0ull, c1 = 0ull, c2 = 0ull, c3 = 0ull;
        #pragma unroll
        for (int j = 0; j < 32; j++) {
            const ulonglong2* kq = (const ulonglong2*)&ksw[j*8];
            ulonglong2 ka = kq[0], kb = kq[1];
            u64 a0 = 0ull, a1 = 0ull;
            FMA2(a0, ka.x, qv0); FMA2(a1, ka.y, qv1);
            FMA2(a0, kb.x, qv2); FMA2(a1, kb.y, qv3);
            float2 f0 = upk2(a0), f1 = upk2(a1);
            float p = exp2f(((f0.x + f0.y) + (f1.x + f1.y)) * CEXP);
            if (j & 1) ssB += p; else ssA += p;
            u64 pp = pk2(p, p);
            const ulonglong2* vq = (const ulonglong2*)&vsw[j*8];
            ulonglong2 va = vq[0], vb = vq[1];
            FMA2(c0, va.x, pp); FMA2(c1, va.y, pp);
            FMA2(c2, vb.x, pp); FMA2(c3, vb.y, pp);
        }

        float inv = 1.f / (ssA + ssB);
        float2 r0 = upk2(c0), r1 = upk2(c1), r2 = upk2(c2), r3 = upk2(c3);
        float vals[8] = {r0.x*inv, r0.y*inv, r1.x*inv, r1.y*inv,
                         r2.x*inv, r2.y*inv, r3.x*inv, r3.y*inv};
        #pragma unroll
        for (int e = 0; e < 8; e++)
            sctx[(head*8 + e)*132 + lane*4 + sw] = vals[e];   // lane = d
    }
    __syncthreads();

    // ---- epilogue GEMM: out[64 c][128 loc] = Wo x ctx, K=64 ----
    // thread (ot = tid&15, nt = tid>>4): 4 c x 8 loc (loc = d*4 + sw).
    {
        int ot = tid & 15, nt = tid >> 4;
        u64 acc[4][4];
        #pragma unroll
        for (int o = 0; o < 4; o++)
            #pragma unroll
            for (int np = 0; np < 4; np++) acc[o][np] = 0ull;

        #pragma unroll 4
        for (int k = 0; k < 64; k++) {
            float4 wt = *(const float4*)&WT[k*64 + ot*4];
            u64 ws[4] = {pk2(wt.x,wt.x), pk2(wt.y,wt.y), pk2(wt.z,wt.z), pk2(wt.w,wt.w)};
            const float4* xp = (const float4*)&sctx[k*132 + nt*8];
            float4 xa = xp[0], xb = xp[1];
            u64 xv[4] = {pk2(xa.x,xa.y), pk2(xa.z,xa.w), pk2(xb.x,xb.y), pk2(xb.z,xb.w)};
            #pragma unroll
            for (int o = 0; o < 4; o++)
                #pragma unroll
                for (int np = 0; np < 4; np++)
                    FMA2(acc[o][np], ws[o], xv[np]);
        }

        // locs nt*8..nt*8+7 = d in {2nt, 2nt+1} x sw 0..3
        float* ob = out + (u64)b*8388608 + s4*4;
        #pragma unroll
        for (int o = 0; o < 4; o++) {
            float* oc = ob + (u64)(ot*4 + o)*131072;
            float2 a0 = upk2(acc[o][0]), a1 = upk2(acc[o][1]);
            float2 a2 = upk2(acc[o][2]), a3 = upk2(acc[o][3]);
            *(float4*)(oc + (u64)(2*nt    )*4096) = make_float4(a0.x, a0.y, a1.x, a1.y);
            *(float4*)(oc + (u64)(2*nt + 1)*4096) = make_float4(a2.x, a2.y, a3.x, a3.y);
        }
    }
}

extern "C" void kernel_launch(void* const* d_in, const int* in_sizes, int n_in,
                              void* d_out, int out_size)
{
    const float* qf = (const float*)d_in[0];
    const float* kf = (const float*)d_in[1];
    const float* Wq = (const float*)d_in[2];
    const float* Wk = (const float*)d_in[3];
    const float* Wv = (const float*)d_in[4];
    const float* Wo = (const float*)d_in[5];
    float* out = (float*)d_out;

    const int ATTN_SMEM = (4096 + 8448 + 4096) * 4;   // 66.6 KB dynamic shared
    cudaFuncSetAttribute(k_attn_o, cudaFuncAttributeMaxDynamicSharedMemorySize,
                         ATTN_SMEM);

    k_proj  <<<1024, 256>>>(qf, Wq, 0);
    k_proj  <<<1024, 256>>>(kf, Wk, 1);
    k_proj  <<<1024, 256>>>(kf, Wv, 2);
    k_attn_o<<<2048, 256, ATTN_SMEM>>>(Wo, out);
}

// round 17
// speedup vs baseline: 1.1985x; 1.1985x over previous
#include <cuda_runtime.h>

#define NEL 16777216   // B*C*D*H*W
typedef unsigned long long u64;

// Scratch: q/k/v in attention layout [b][s][head][d][e].
__device__ __align__(16) float g_q[NEL];
__device__ __align__(16) float g_k[NEL];
__device__ __align__(16) float g_v[NEL];

__device__ __forceinline__ u64 pk2(float lo, float hi) {
    u64 r; asm("mov.b64 %0, {%1,%2};" : "=l"(r) : "f"(lo), "f"(hi)); return r;
}
__device__ __forceinline__ float2 upk2(u64 v) {
    float2 r; asm("mov.b64 {%0,%1}, %2;" : "=f"(r.x), "=f"(r.y) : "l"(v)); return r;
}
#define FMA2(d, a, b) asm("fma.rn.f32x2 %0, %1, %2, %0;" : "+l"(d) : "l"(a), "l"(b))

// ---------------------------------------------------------------------------
// W[64][64] ([o][k]) -> two conflict-free planes, 16B stride over ot. (proven)
// ---------------------------------------------------------------------------
__device__ __forceinline__ void stage_W2(float* A, float* B,
                                         const float* __restrict__ Wsrc) {
    for (int idx = threadIdx.x; idx < 2048; idx += 256) {
        int k = idx >> 5, t = idx & 31;
        int ot = t >> 2, j = t & 3;
        A[idx] = Wsrc[(ot*8 + j)*64 + k];
        B[idx] = Wsrc[(ot*8 + 4 + j)*64 + k];
    }
}

__device__ __forceinline__ void stage_chunk(float* xs, const float* __restrict__ xsrc,
                                            int b, int n0, int kc) {
    const float4* xg = (const float4*)(xsrc + (u64)b*8388608 + n0);
    float4* xs4 = (float4*)xs;
    #pragma unroll
    for (int i = 0; i < 8; i++) {
        int idx = threadIdx.x + i*256;
        int c = idx >> 6, n4 = idx & 63;
        xs4[c*64 + n4] = xg[(u64)(kc*32 + c)*32768 + n4];
    }
}

// ---------------------------------------------------------------------------
// Q projection (proven R14 k_proj, unchanged; natural regs, no cap abuse).
// ---------------------------------------------------------------------------
__global__ void __launch_bounds__(256, 2) k_proj(const float* __restrict__ x,
                                                 const float* __restrict__ W,
                                                 int which)
{
    __shared__ __align__(16) float xs[32*256];
    __shared__ __align__(16) float WA[2048];
    __shared__ __align__(16) float WB[2048];
    float* dst = (which == 0) ? g_q : (which == 1) ? g_k : g_v;
    int b = blockIdx.x >> 9;
    int n0 = (blockIdx.x & 511) << 8;
    stage_W2(WA, WB, W);

    int ot = threadIdx.x & 7, nt = threadIdx.x >> 3;
    u64 acc[8][4];
    #pragma unroll
    for (int o = 0; o < 8; o++)
        #pragma unroll
        for (int np = 0; np < 4; np++) acc[o][np] = 0ull;

    #pragma unroll 1
    for (int kc = 0; kc < 2; kc++) {
        __syncthreads();
        stage_chunk(xs, x, b, n0, kc);
        __syncthreads();
        #pragma unroll 4
        for (int k = 0; k < 32; k++) {
            int kg = kc*32 + k;
            float4 wa = *(const float4*)&WA[kg*32 + ot*4];
            float4 wb = *(const float4*)&WB[kg*32 + ot*4];
            u64 ws[8] = {pk2(wa.x,wa.x), pk2(wa.y,wa.y), pk2(wa.z,wa.z), pk2(wa.w,wa.w),
                         pk2(wb.x,wb.x), pk2(wb.y,wb.y), pk2(wb.z,wb.z), pk2(wb.w,wb.w)};
            const ulonglong2* xp = (const ulonglong2*)&xs[k*256 + nt*8];
            ulonglong2 x0 = xp[0], x1 = xp[1];
            u64 xv[4] = {x0.x, x0.y, x1.x, x1.y};
            #pragma unroll
            for (int o = 0; o < 8; o++)
                #pragma unroll
                for (int np = 0; np < 4; np++)
                    FMA2(acc[o][np], ws[o], xv[np]);
        }
    }

    int d = n0 >> 12;
    int sb = (n0 & 4095) + nt*8;
    float* gq = dst + (u64)b*8388608 + ot*256 + d*8;
    #pragma unroll
    for (int np = 0; np < 4; np++) {
        float2 f[8];
        #pragma unroll
        for (int o = 0; o < 8; o++) f[o] = upk2(acc[o][np]);
        float* p0 = gq + (u64)(sb + 2*np)*2048;
        ((float4*)p0)[0] = make_float4(f[0].x, f[1].x, f[2].x, f[3].x);
        ((float4*)p0)[1] = make_float4(f[4].x, f[5].x, f[6].x, f[7].x);
        float* p1 = gq + (u64)(sb + 2*np + 1)*2048;
        ((float4*)p1)[0] = make_float4(f[0].y, f[1].y, f[2].y, f[3].y);
        ((float4*)p1)[1] = make_float4(f[4].y, f[5].y, f[6].y, f[7].y);
    }
}

// ---------------------------------------------------------------------------
// Fused K+V projection: one x-staging feeds both GEMMs.
// Block [64o x 128n], 256 threads, thread tile [8o x 4n] per matrix.
// acc = 64 regs; smem 48KB; no reg cap (avoid R16 spill failure).
// ---------------------------------------------------------------------------
__global__ void __launch_bounds__(256) k_proj_kv(const float* __restrict__ x,
                                                 const float* __restrict__ Wk,
                                                 const float* __restrict__ Wv)
{
    __shared__ __align__(16) float xs[32*128];
    __shared__ __align__(16) float KA[2048], KB[2048];
    __shared__ __align__(16) float VA[2048], VB[2048];
    int b = blockIdx.x >> 10;
    int n0 = (blockIdx.x & 1023) << 7;
    stage_W2(KA, KB, Wk);
    stage_W2(VA, VB, Wv);

    int ot = threadIdx.x & 7, nt = threadIdx.x >> 3;   // n = nt*4
    u64 ak[8][2], av[8][2];
    #pragma unroll
    for (int o = 0; o < 8; o++)
        #pragma unroll
        for (int np = 0; np < 2; np++) { ak[o][np] = 0ull; av[o][np] = 0ull; }

    #pragma unroll 1
    for (int kc = 0; kc < 2; kc++) {
        __syncthreads();
        {
            const float4* xg = (const float4*)(x + (u64)b*8388608 + n0);
            float4* xs4 = (float4*)xs;
            #pragma unroll
            for (int i = 0; i < 4; i++) {
                int idx = threadIdx.x + i*256;
                int c = idx >> 5, n4 = idx & 31;
                xs4[c*32 + n4] = xg[(u64)(kc*32 + c)*32768 + n4];
            }
        }
        __syncthreads();
        #pragma unroll 4
        for (int k = 0; k < 32; k++) {
            int kg = kc*32 + k;
            const ulonglong2* xp = (const ulonglong2*)&xs[k*128 + nt*4];
            ulonglong2 x0 = xp[0];
            u64 xv[2] = {x0.x, x0.y};
            {
                float4 wa = *(const float4*)&KA[kg*32 + ot*4];
                float4 wb = *(const float4*)&KB[kg*32 + ot*4];
                u64 ws[8] = {pk2(wa.x,wa.x), pk2(wa.y,wa.y), pk2(wa.z,wa.z), pk2(wa.w,wa.w),
                             pk2(wb.x,wb.x), pk2(wb.y,wb.y), pk2(wb.z,wb.z), pk2(wb.w,wb.w)};
                #pragma unroll
                for (int o = 0; o < 8; o++) {
                    FMA2(ak[o][0], ws[o], xv[0]);
                    FMA2(ak[o][1], ws[o], xv[1]);
                }
            }
            {
                float4 wa = *(const float4*)&VA[kg*32 + ot*4];
                float4 wb = *(const float4*)&VB[kg*32 + ot*4];
                u64 ws[8] = {pk2(wa.x,wa.x), pk2(wa.y,wa.y), pk2(wa.z,wa.z), pk2(wa.w,wa.w),
                             pk2(wb.x,wb.x), pk2(wb.y,wb.y), pk2(wb.z,wb.z), pk2(wb.w,wb.w)};
                #pragma unroll
                for (int o = 0; o < 8; o++) {
                    FMA2(av[o][0], ws[o], xv[0]);
                    FMA2(av[o][1], ws[o], xv[1]);
                }
            }
        }
    }

    int d = n0 >> 12;
    int sb = (n0 & 4095) + nt*4;
    u64 boff = (u64)b*8388608 + ot*256 + d*8;
    #pragma unroll
    for (int np = 0; np < 2; np++) {
        float2 fk[8], fv[8];
        #pragma unroll
        for (int o = 0; o < 8; o++) { fk[o] = upk2(ak[o][np]); fv[o] = upk2(av[o][np]); }
        u64 s0 = (u64)(sb + 2*np)*2048, s1 = (u64)(sb + 2*np + 1)*2048;
        float* p;
        p = g_k + boff + s0;
        ((float4*)p)[0] = make_float4(fk[0].x, fk[1].x, fk[2].x, fk[3].x);
        ((float4*)p)[1] = make_float4(fk[4].x, fk[5].x, fk[6].x, fk[7].x);
        p = g_k + boff + s1;
        ((float4*)p)[0] = make_float4(fk[0].y, fk[1].y, fk[2].y, fk[3].y);
        ((float4*)p)[1] = make_float4(fk[4].y, fk[5].y, fk[6].y, fk[7].y);
        p = g_v + boff + s0;
        ((float4*)p)[0] = make_float4(fv[0].x, fv[1].x, fv[2].x, fv[3].x);
        ((float4*)p)[1] = make_float4(fv[4].x, fv[5].x, fv[6].x, fv[7].x);
        p = g_v + boff + s1;
        ((float4*)p)[0] = make_float4(fv[0].y, fv[1].y, fv[2].y, fv[3].y);
        ((float4*)p)[1] = make_float4(fv[4].y, fv[5].y, fv[6].y, fv[7].y);
    }
}

// ---------------------------------------------------------------------------
// Fused attention + O projection (R14, proven best — unchanged).
// ---------------------------------------------------------------------------
__global__ void __launch_bounds__(512) k_attn_o(const float* __restrict__ Wo,
                                                float* __restrict__ out)
{
    extern __shared__ __align__(16) float sm[];
    float* ksw  = sm + threadIdx.x / 32 * 256;
    float* vsw  = sm + 4096 + threadIdx.x / 32 * 256;
    float* sctx = sm + 8192;
    float* WT   = sm + 8192 + 24576;

    int tid = threadIdx.x;
    int warp = tid >> 5, lane = tid & 31;
    int sw = warp & 7, hh = warp >> 3;
    int blk = blockIdx.x;
    int s8 = blk & 511, b = blk >> 9;
    int s = s8*8 + sw;

    for (int idx = tid; idx < 4096; idx += 512)
        WT[idx] = Wo[(idx & 63)*64 + (idx >> 6)];

    const float CEXP = 0.35355339059327373f * 1.4426950408889634f;

    #pragma unroll 1
    for (int hi = 0; hi < 4; hi++) {
        int head = hh*4 + hi;
        u64 u = (u64)(((b << 12) + s)*8 + head);

        __syncwarp();
        {
            const float4* kp = (const float4*)(g_k + u*256);
            const float4* vp = (const float4*)(g_v + u*256);
            ((float4*)ksw)[lane*2]     = kp[lane*2];
            ((float4*)ksw)[lane*2 + 1] = kp[lane*2 + 1];
            ((float4*)vsw)[lane*2]     = vp[lane*2];
            ((float4*)vsw)[lane*2 + 1] = vp[lane*2 + 1];
        }
        const float4* qp = (const float4*)(g_q + u*256 + lane*8);
        float4 q0 = qp[0], q1 = qp[1];
        u64 qv0 = pk2(q0.x, q0.y), qv1 = pk2(q0.z, q0.w);
        u64 qv2 = pk2(q1.x, q1.y), qv3 = pk2(q1.z, q1.w);
        __syncwarp();

        float ssA = 0.f, ssB = 0.f;
        u64 c0 = 0ull, c1 = 0ull, c2 = 0ull, c3 = 0ull;
        #pragma unroll
        for (int j = 0; j < 32; j++) {
            const ulonglong2* kq = (const ulonglong2*)&ksw[j*8];
            ulonglong2 ka = kq[0], kb = kq[1];
            u64 a0 = 0ull, a1 = 0ull;
            FMA2(a0, ka.x, qv0); FMA2(a1, ka.y, qv1);
            FMA2(a0, kb.x, qv2); FMA2(a1, kb.y, qv3);
            float2 f0 = upk2(a0), f1 = upk2(a1);
            float p = exp2f(((f0.x + f0.y) + (f1.x + f1.y)) * CEXP);
            if (j & 1) ssB += p; else ssA += p;
            u64 pp = pk2(p, p);
            const ulonglong2* vq = (const ulonglong2*)&vsw[j*8];
            ulonglong2 va = vq[0], vb = vq[1];
            FMA2(c0, va.x, pp); FMA2(c1, va.y, pp);
            FMA2(c2, vb.x, pp); FMA2(c3, vb.y, pp);
        }

        float inv = 1.f / (ssA + ssB);
        float2 r0 = upk2(c0), r1 = upk2(c1), r2 = upk2(c2), r3 = upk2(c3);
        float vals[8] = {r0.x*inv, r0.y*inv, r1.x*inv, r1.y*inv,
                         r2.x*inv, r2.y*inv, r3.x*inv, r3.y*inv};
        #pragma unroll
        for (int e = 0; e < 8; e++)
            sctx[(head*8 + e)*384 + lane*12 + sw] = vals[e];
    }
    __syncthreads();

    {
        int ot = tid & 15, nt = tid >> 4;
        u64 acc[4][4];
        #pragma unroll
        for (int o = 0; o < 4; o++)
            #pragma unroll
            for (int np = 0; np < 4; np++) acc[o][np] = 0ull;

        #pragma unroll 4
        for (int k = 0; k < 64; k++) {
            float4 wt = *(const float4*)&WT[k*64 + ot*4];
            u64 ws[4] = {pk2(wt.x,wt.x), pk2(wt.y,wt.y), pk2(wt.z,wt.z), pk2(wt.w,wt.w)};
            const float4* xp = (const float4*)&sctx[k*384 + nt*12];
            float4 xa = xp[0], xb = xp[1];
            u64 xv[4] = {pk2(xa.x,xa.y), pk2(xa.z,xa.w), pk2(xb.x,xb.y), pk2(xb.z,xb.w)};
            #pragma unroll
            for (int o = 0; o < 4; o++)
                #pragma unroll
                for (int np = 0; np < 4; np++)
                    FMA2(acc[o][np], ws[o], xv[np]);
        }

        float* ob = out + (u64)b*8388608 + nt*4096 + s8*8;
        #pragma unroll
        for (int o = 0; o < 4; o++) {
            float* oc = ob + (u64)(ot*4 + o)*131072;
            float2 a0 = upk2(acc[o][0]), a1 = upk2(acc[o][1]);
            float2 a2 = upk2(acc[o][2]), a3 = upk2(acc[o][3]);
            ((float4*)oc)[0] = make_float4(a0.x, a0.y, a1.x, a1.y);
            ((float4*)oc)[1] = make_float4(a2.x, a2.y, a3.x, a3.y);
        }
    }
}

extern "C" void kernel_launch(void* const* d_in, const int* in_sizes, int n_in,
                              void* d_out, int out_size)
{
    const float* qf = (const float*)d_in[0];
    const float* kf = (const float*)d_in[1];
    const float* Wq = (const float*)d_in[2];
    const float* Wk = (const float*)d_in[3];
    const float* Wv = (const float*)d_in[4];
    const float* Wo = (const float*)d_in[5];
    float* out = (float*)d_out;

    const int ATTN_SMEM = 36864 * 4;   // 144 KB dynamic shared
    cudaFuncSetAttribute(k_attn_o, cudaFuncAttributeMaxDynamicSharedMemorySize,
                         ATTN_SMEM);

    k_proj   <<<1024, 256>>>(qf, Wq, 0);
    k_proj_kv<<<2048, 256>>>(kf, Wk, Wv);
    k_attn_o <<<1024, 512, ATTN_SMEM>>>(Wo, out);
}